// round 2
// baseline (speedup 1.0000x reference)
#include <cuda_runtime.h>

#define DIMC 64
#define N_MAX 50048
#define E_MAX 800000
#define NEG_SLOPE 0.3f
#define BN_EPS 1e-5f

// Scratch (static __device__ per allocation rules)
__device__ __align__(16) float g_A[N_MAX * DIMC];   // feat @ (W1-W2)^T + b   (dst side)
__device__ __align__(16) float g_B[N_MAX * DIMC];   // feat @ W2^T            (src side)
__device__ __align__(16) float g_wt[64 * 128];      // transformed weights, [k][c] layout
__device__ float g_sum[DIMC];
__device__ float g_sumsq[DIMC];
__device__ float g_scale[DIMC];
__device__ float g_shift[DIMC];
__device__ int g_cnt[N_MAX];
__device__ int g_cursor[N_MAX];
__device__ int g_off[N_MAX];
__device__ int g_bsum[64];
__device__ int g_boff[64];
__device__ int g_srcs[E_MAX];

__global__ void k_zero(int n_nodes) {
    int i = blockIdx.x * blockDim.x + threadIdx.x;
    if (i < n_nodes) { g_cnt[i] = 0; g_cursor[i] = 0; }
    if (i < DIMC) { g_sum[i] = 0.f; g_sumsq[i] = 0.f; }
}

// Build wt[k*128 + c]: c<64 -> W1-W2 column, c>=64 -> W2 column
__global__ void k_prepw(const float* __restrict__ W) {
    int i = blockIdx.x * blockDim.x + threadIdx.x;
    if (i >= 64 * 128) return;
    int k = i >> 7, c = i & 127;
    float v;
    if (c < 64) v = W[c * 128 + k] - W[c * 128 + 64 + k];
    else        v = W[(c - 64) * 128 + 64 + k];
    g_wt[i] = v;
}

// Per-node transform: block handles 32 nodes x 128 output cols, 4x4 register tile per thread
__global__ __launch_bounds__(256) void k_transform(const float* __restrict__ feat,
                                                   const float* __restrict__ b,
                                                   int n_nodes) {
    __shared__ __align__(16) float wt[64 * 128];
    __shared__ float ft[32][65];
    int tid = threadIdx.x;
    for (int i = tid; i < 64 * 128; i += 256) wt[i] = g_wt[i];
    int node0 = blockIdx.x * 32;
    {
        int k = tid & 63;
        for (int nn = tid >> 6; nn < 32; nn += 4) {
            int n = node0 + nn;
            ft[nn][k] = (n < n_nodes) ? feat[n * 64 + k] : 0.f;
        }
    }
    __syncthreads();
    int cg = tid & 31;   // cols cg*4 .. cg*4+3  (0..127)
    int ng = tid >> 5;   // nodes ng*4 .. ng*4+3 (0..31)
    float a0[4], a1[4], a2[4], a3[4];
#pragma unroll
    for (int j = 0; j < 4; j++) { a0[j] = a1[j] = a2[j] = a3[j] = 0.f; }
    const float4* wt4 = (const float4*)wt;
#pragma unroll 8
    for (int k = 0; k < 64; k++) {
        float4 w = wt4[k * 32 + cg];
#pragma unroll
        for (int j = 0; j < 4; j++) {
            float f = ft[ng * 4 + j][k];
            a0[j] += f * w.x; a1[j] += f * w.y; a2[j] += f * w.z; a3[j] += f * w.w;
        }
    }
    int c0 = cg * 4;
#pragma unroll
    for (int j = 0; j < 4; j++) {
        int n = node0 + ng * 4 + j;
        if (n >= n_nodes) continue;
        if (c0 < 64) {
            float4 v = make_float4(a0[j] + b[c0], a1[j] + b[c0 + 1],
                                   a2[j] + b[c0 + 2], a3[j] + b[c0 + 3]);
            *(float4*)&g_A[n * 64 + c0] = v;
        } else {
            float4 v = make_float4(a0[j], a1[j], a2[j], a3[j]);
            *(float4*)&g_B[n * 64 + (c0 - 64)] = v;
        }
    }
}

// Edge pass 1: BN statistics (sum, sumsq per channel) + in-degree counts.
// Warp handles 2 edges per iter; 16 lanes x float4 covers the 64 channels of one edge.
__global__ __launch_bounds__(256) void k_pass1(const int* __restrict__ ei, int E, int n_nodes) {
    __shared__ float bs[64], bq[64];
    int tid = threadIdx.x;
    if (tid < 64) { bs[tid] = 0.f; bq[tid] = 0.f; }
    __syncthreads();
    int lane = tid & 31;
    int sub = lane >> 4;
    int q = lane & 15;
    int gw = (blockIdx.x * blockDim.x + tid) >> 5;
    int nw = (gridDim.x * blockDim.x) >> 5;
    float s0 = 0, s1 = 0, s2 = 0, s3 = 0, q0 = 0, q1 = 0, q2 = 0, q3 = 0;
    for (int e0 = gw * 2; e0 < E; e0 += nw * 2) {
        int e = e0 + sub;
        if (e < E) {
            int sn = ei[e];
            int dn = ei[E + e];
            if ((unsigned)sn < (unsigned)n_nodes && (unsigned)dn < (unsigned)n_nodes) {
                float4 a = *(const float4*)&g_A[dn * 64 + q * 4];
                float4 bb = *(const float4*)&g_B[sn * 64 + q * 4];
                float h0 = a.x + bb.x, h1 = a.y + bb.y, h2 = a.z + bb.z, h3 = a.w + bb.w;
                s0 += h0; s1 += h1; s2 += h2; s3 += h3;
                q0 += h0 * h0; q1 += h1 * h1; q2 += h2 * h2; q3 += h3 * h3;
                if (q == 0) atomicAdd(&g_cnt[dn], 1);
            }
        }
    }
    atomicAdd(&bs[q * 4 + 0], s0); atomicAdd(&bs[q * 4 + 1], s1);
    atomicAdd(&bs[q * 4 + 2], s2); atomicAdd(&bs[q * 4 + 3], s3);
    atomicAdd(&bq[q * 4 + 0], q0); atomicAdd(&bq[q * 4 + 1], q1);
    atomicAdd(&bq[q * 4 + 2], q2); atomicAdd(&bq[q * 4 + 3], q3);
    __syncthreads();
    if (tid < 64) { atomicAdd(&g_sum[tid], bs[tid]); atomicAdd(&g_sumsq[tid], bq[tid]); }
}

__global__ void k_bnfinal(const float* __restrict__ gamma, const float* __restrict__ beta, int E) {
    int c = threadIdx.x;
    if (c < 64) {
        float invE = 1.f / (float)E;
        float mean = g_sum[c] * invE;
        float var = g_sumsq[c] * invE - mean * mean;
        float s = gamma[c] * rsqrtf(var + BN_EPS);
        g_scale[c] = s;
        g_shift[c] = beta[c] - mean * s;
    }
}

// CSR construction: exclusive scan of counts (3 tiny kernels) + bucket fill.
__global__ __launch_bounds__(1024) void k_scan1(int n_nodes) {
    __shared__ int sh[1024];
    int t = threadIdx.x;
    int i = blockIdx.x * 1024 + t;
    int v = (i < n_nodes) ? g_cnt[i] : 0;
    sh[t] = v;
    __syncthreads();
    for (int d = 1; d < 1024; d <<= 1) {
        int x = (t >= d) ? sh[t - d] : 0;
        __syncthreads();
        sh[t] += x;
        __syncthreads();
    }
    if (i < n_nodes) g_off[i] = sh[t] - v;   // exclusive scan (local)
    if (t == 1023) g_bsum[blockIdx.x] = sh[1023];
}

__global__ void k_scan2(int nblocks) {
    if (threadIdx.x == 0) {
        int run = 0;
        for (int bk = 0; bk < nblocks; bk++) { g_boff[bk] = run; run += g_bsum[bk]; }
    }
}

__global__ void k_scan3(int n_nodes) {
    int i = blockIdx.x * blockDim.x + threadIdx.x;
    if (i < n_nodes) g_off[i] += g_boff[i >> 10];
}

__global__ __launch_bounds__(256) void k_fill(const int* __restrict__ ei, int E, int n_nodes) {
    int stride = gridDim.x * blockDim.x;
    for (int e = blockIdx.x * blockDim.x + threadIdx.x; e < E; e += stride) {
        int sn = ei[e];
        int dn = ei[E + e];
        if ((unsigned)sn >= (unsigned)n_nodes || (unsigned)dn >= (unsigned)n_nodes) continue;
        int pos = g_off[dn] + atomicAdd(&g_cursor[dn], 1);
        if (pos >= 0 && pos < E_MAX) g_srcs[pos] = sn;
    }
}

// Node-centric gather: one warp per node, A[n]+scale/shift in registers, stream B[src].
// No output atomics; fuses BN affine, LeakyReLU, and the mean divide.
__global__ __launch_bounds__(256) void k_gather(float* __restrict__ out, int n_nodes) {
    int lane = threadIdx.x & 31;
    int n = (blockIdx.x * blockDim.x + threadIdx.x) >> 5;
    if (n >= n_nodes) return;
    int c = lane * 2;
    float2 a = *(const float2*)&g_A[n * 64 + c];
    float sc0 = g_scale[c], sc1 = g_scale[c + 1];
    float sh0 = g_shift[c], sh1 = g_shift[c + 1];
    int start = g_off[n];
    int deg = g_cnt[n];
    int end = start + deg;
    float acc0 = 0.f, acc1 = 0.f;
    int i = start;
    for (; i + 1 < end; i += 2) {
        int sA = g_srcs[i], sB = g_srcs[i + 1];
        float2 bA = *(const float2*)&g_B[sA * 64 + c];
        float2 bB = *(const float2*)&g_B[sB * 64 + c];
        float y;
        y = (a.x + bA.x) * sc0 + sh0; acc0 += fmaxf(y, NEG_SLOPE * y);
        y = (a.y + bA.y) * sc1 + sh1; acc1 += fmaxf(y, NEG_SLOPE * y);
        y = (a.x + bB.x) * sc0 + sh0; acc0 += fmaxf(y, NEG_SLOPE * y);
        y = (a.y + bB.y) * sc1 + sh1; acc1 += fmaxf(y, NEG_SLOPE * y);
    }
    if (i < end) {
        int sA = g_srcs[i];
        float2 bA = *(const float2*)&g_B[sA * 64 + c];
        float y;
        y = (a.x + bA.x) * sc0 + sh0; acc0 += fmaxf(y, NEG_SLOPE * y);
        y = (a.y + bA.y) * sc1 + sh1; acc1 += fmaxf(y, NEG_SLOPE * y);
    }
    float inv = 1.f / fmaxf((float)deg, 1.f);
    *(float2*)&out[n * 64 + c] = make_float2(acc0 * inv, acc1 * inv);
}

extern "C" void kernel_launch(void* const* d_in, const int* in_sizes, int n_in,
                              void* d_out, int out_size) {
    const float* feat = (const float*)d_in[0];
    const int* ei = (const int*)d_in[1];
    const float* W = (const float*)d_in[2];
    const float* b = (const float*)d_in[3];
    const float* gamma = (const float*)d_in[4];
    const float* beta = (const float*)d_in[5];
    float* out = (float*)d_out;

    int n_nodes = in_sizes[0] / DIMC;
    int E = in_sizes[1] / 2;
    if (n_nodes > N_MAX) n_nodes = N_MAX;
    if (E > E_MAX) E = E_MAX;

    k_zero<<<(n_nodes + 255) / 256, 256>>>(n_nodes);
    k_prepw<<<32, 256>>>(W);
    k_transform<<<(n_nodes + 31) / 32, 256>>>(feat, b, n_nodes);
    k_pass1<<<1024, 256>>>(ei, E, n_nodes);
    k_bnfinal<<<1, 64>>>(gamma, beta, E);
    int sblocks = (n_nodes + 1023) / 1024;
    k_scan1<<<sblocks, 1024>>>(n_nodes);
    k_scan2<<<1, 32>>>(sblocks);
    k_scan3<<<(n_nodes + 255) / 256, 256>>>(n_nodes);
    k_fill<<<1024, 256>>>(ei, E, n_nodes);
    k_gather<<<(n_nodes * 32 + 255) / 256, 256>>>(out, n_nodes);
}

// round 3
// speedup vs baseline: 1.0559x; 1.0559x over previous
#include <cuda_runtime.h>

#define DIMC 64
#define N_MAX 50048
#define E_MAX 800000
#define NEG_SLOPE 0.3f
#define BN_EPS 1e-5f

// Scratch (static __device__ per allocation rules)
__device__ __align__(16) float g_A[N_MAX * DIMC];   // feat @ (W1-W2)^T + b   (dst side)
__device__ __align__(16) float g_B[N_MAX * DIMC];   // feat @ W2^T            (src side)
__device__ __align__(16) float g_wt[64 * 128];      // transformed weights, [k][c] layout
__device__ float g_sum[DIMC];
__device__ float g_sumsq[DIMC];
__device__ float g_scale[DIMC];
__device__ float g_shift[DIMC];
__device__ int g_cnt[N_MAX];
__device__ int g_cursor[N_MAX];
__device__ int g_off[N_MAX];     // exclusive scan, block-local (add g_boff at use)
__device__ int g_bsum[64];
__device__ int g_boff[64];
__device__ int g_srcs[E_MAX];

// Fused init: zero counters/stats + build transformed weights
__global__ void k_init(const float* __restrict__ W, int n_nodes) {
    int i = blockIdx.x * blockDim.x + threadIdx.x;
    if (i < n_nodes) { g_cnt[i] = 0; g_cursor[i] = 0; }
    if (i < DIMC) { g_sum[i] = 0.f; g_sumsq[i] = 0.f; }
    if (i < 64 * 128) {
        int k = i >> 7, c = i & 127;
        float v;
        if (c < 64) v = W[c * 128 + k] - W[c * 128 + 64 + k];
        else        v = W[(c - 64) * 128 + 64 + k];
        g_wt[i] = v;
    }
}

// Per-node transform: block = 64 nodes x 128 output cols; 4-col x 8-node register tile.
__global__ __launch_bounds__(256) void k_transform(const float* __restrict__ feat,
                                                   const float* __restrict__ b,
                                                   int n_nodes) {
    __shared__ __align__(16) float wt[64 * 128];   // 32 KB
    __shared__ float ft[64][64];                   // 16 KB (reads are warp-broadcast)
    int tid = threadIdx.x;
    {
        const float4* src = (const float4*)g_wt;
        float4* dst = (float4*)wt;
        for (int i = tid; i < 64 * 128 / 4; i += 256) dst[i] = src[i];
    }
    int node0 = blockIdx.x * 64;
    {
        int k = tid & 63;
        for (int nn = tid >> 6; nn < 64; nn += 4) {
            int n = node0 + nn;
            ft[nn][k] = (n < n_nodes) ? feat[n * 64 + k] : 0.f;
        }
    }
    __syncthreads();
    int cg = tid & 31;   // cols cg*4 .. cg*4+3  (0..127)
    int ng = tid >> 5;   // nodes ng*8 .. ng*8+7 (0..63)
    float a0[8], a1[8], a2[8], a3[8];
#pragma unroll
    for (int j = 0; j < 8; j++) { a0[j] = a1[j] = a2[j] = a3[j] = 0.f; }
    const float4* wt4 = (const float4*)wt;
#pragma unroll 4
    for (int k = 0; k < 64; k++) {
        float4 w = wt4[k * 32 + cg];
#pragma unroll
        for (int j = 0; j < 8; j++) {
            float f = ft[ng * 8 + j][k];
            a0[j] += f * w.x; a1[j] += f * w.y; a2[j] += f * w.z; a3[j] += f * w.w;
        }
    }
    int c0 = cg * 4;
#pragma unroll
    for (int j = 0; j < 8; j++) {
        int n = node0 + ng * 8 + j;
        if (n >= n_nodes) continue;
        if (c0 < 64) {
            float4 v = make_float4(a0[j] + b[c0], a1[j] + b[c0 + 1],
                                   a2[j] + b[c0 + 2], a3[j] + b[c0 + 3]);
            *(float4*)&g_A[n * 64 + c0] = v;
        } else {
            float4 v = make_float4(a0[j], a1[j], a2[j], a3[j]);
            *(float4*)&g_B[n * 64 + (c0 - 64)] = v;
        }
    }
}

// In-degree counts from the dst row only (vectorized int4).
__global__ __launch_bounds__(256) void k_count(const int* __restrict__ ei, int E, int n_nodes) {
    const int* dstrow = ei + E;
    int E4 = E >> 2;
    int stride = gridDim.x * blockDim.x;
    const int4* d4 = (const int4*)dstrow;
    for (int i = blockIdx.x * blockDim.x + threadIdx.x; i < E4; i += stride) {
        int4 v = d4[i];
        if ((unsigned)v.x < (unsigned)n_nodes) atomicAdd(&g_cnt[v.x], 1);
        if ((unsigned)v.y < (unsigned)n_nodes) atomicAdd(&g_cnt[v.y], 1);
        if ((unsigned)v.z < (unsigned)n_nodes) atomicAdd(&g_cnt[v.z], 1);
        if ((unsigned)v.w < (unsigned)n_nodes) atomicAdd(&g_cnt[v.w], 1);
    }
    // tail
    for (int e = (E4 << 2) + blockIdx.x * blockDim.x + threadIdx.x; e < E; e += stride) {
        int dn = dstrow[e];
        if ((unsigned)dn < (unsigned)n_nodes) atomicAdd(&g_cnt[dn], 1);
    }
}

// CSR construction: exclusive scan of counts + bucket fill.
__global__ __launch_bounds__(1024) void k_scan1(int n_nodes) {
    __shared__ int sh[1024];
    int t = threadIdx.x;
    int i = blockIdx.x * 1024 + t;
    int v = (i < n_nodes) ? g_cnt[i] : 0;
    sh[t] = v;
    __syncthreads();
    for (int d = 1; d < 1024; d <<= 1) {
        int x = (t >= d) ? sh[t - d] : 0;
        __syncthreads();
        sh[t] += x;
        __syncthreads();
    }
    if (i < n_nodes) g_off[i] = sh[t] - v;   // exclusive (block-local)
    if (t == 1023) g_bsum[blockIdx.x] = sh[1023];
}

__global__ void k_scan2(int nblocks) {
    if (threadIdx.x == 0) {
        int run = 0;
        for (int bk = 0; bk < nblocks; bk++) { g_boff[bk] = run; run += g_bsum[bk]; }
    }
}

__global__ __launch_bounds__(256) void k_fill(const int* __restrict__ ei, int E, int n_nodes) {
    int stride = gridDim.x * blockDim.x;
    for (int e = blockIdx.x * blockDim.x + threadIdx.x; e < E; e += stride) {
        int sn = ei[e];
        int dn = ei[E + e];
        if ((unsigned)sn >= (unsigned)n_nodes || (unsigned)dn >= (unsigned)n_nodes) continue;
        int pos = g_off[dn] + g_boff[dn >> 10] + atomicAdd(&g_cursor[dn], 1);
        if (pos >= 0 && pos < E_MAX) g_srcs[pos] = sn;
    }
}

// Node-centric BN stats over CSR: A row read once per node, B streamed per edge.
// Persistent grid; block-level staging before 128 global atomics per block.
__global__ __launch_bounds__(256) void k_stats(int n_nodes) {
    __shared__ float smS[64], smQ[64];
    int tid = threadIdx.x;
    if (tid < 64) { smS[tid] = 0.f; smQ[tid] = 0.f; }
    __syncthreads();
    int lane = tid & 31;
    int c = lane * 2;
    int gw = (blockIdx.x * blockDim.x + tid) >> 5;
    int nw = (gridDim.x * blockDim.x) >> 5;
    float s0 = 0.f, s1 = 0.f, q0 = 0.f, q1 = 0.f;
    for (int n = gw; n < n_nodes; n += nw) {
        float2 a = *(const float2*)&g_A[n * 64 + c];
        int off = g_off[n] + g_boff[n >> 10];
        int end = off + g_cnt[n];
        int i = off;
        for (; i + 3 < end; i += 4) {
            int sA = g_srcs[i], sB = g_srcs[i + 1], sC = g_srcs[i + 2], sD = g_srcs[i + 3];
            float2 bA = *(const float2*)&g_B[sA * 64 + c];
            float2 bB = *(const float2*)&g_B[sB * 64 + c];
            float2 bC = *(const float2*)&g_B[sC * 64 + c];
            float2 bD = *(const float2*)&g_B[sD * 64 + c];
            float h;
            h = a.x + bA.x; s0 += h; q0 += h * h;
            h = a.y + bA.y; s1 += h; q1 += h * h;
            h = a.x + bB.x; s0 += h; q0 += h * h;
            h = a.y + bB.y; s1 += h; q1 += h * h;
            h = a.x + bC.x; s0 += h; q0 += h * h;
            h = a.y + bC.y; s1 += h; q1 += h * h;
            h = a.x + bD.x; s0 += h; q0 += h * h;
            h = a.y + bD.y; s1 += h; q1 += h * h;
        }
        for (; i < end; i++) {
            int sA = g_srcs[i];
            float2 bA = *(const float2*)&g_B[sA * 64 + c];
            float h;
            h = a.x + bA.x; s0 += h; q0 += h * h;
            h = a.y + bA.y; s1 += h; q1 += h * h;
        }
    }
    atomicAdd(&smS[c], s0); atomicAdd(&smS[c + 1], s1);
    atomicAdd(&smQ[c], q0); atomicAdd(&smQ[c + 1], q1);
    __syncthreads();
    if (tid < 64) { atomicAdd(&g_sum[tid], smS[tid]); atomicAdd(&g_sumsq[tid], smQ[tid]); }
}

__global__ void k_bnfinal(const float* __restrict__ gamma, const float* __restrict__ beta, int E) {
    int c = threadIdx.x;
    if (c < 64) {
        float invE = 1.f / (float)E;
        float mean = g_sum[c] * invE;
        float var = g_sumsq[c] * invE - mean * mean;
        float s = gamma[c] * rsqrtf(var + BN_EPS);
        g_scale[c] = s;
        g_shift[c] = beta[c] - mean * s;
    }
}

// Node-centric gather: one warp per node; fuses BN affine, LeakyReLU, mean divide.
__global__ __launch_bounds__(256) void k_gather(float* __restrict__ out, int n_nodes) {
    int lane = threadIdx.x & 31;
    int n = (blockIdx.x * blockDim.x + threadIdx.x) >> 5;
    if (n >= n_nodes) return;
    int c = lane * 2;
    float2 a = *(const float2*)&g_A[n * 64 + c];
    float sc0 = g_scale[c], sc1 = g_scale[c + 1];
    float sh0 = g_shift[c], sh1 = g_shift[c + 1];
    int start = g_off[n] + g_boff[n >> 10];
    int deg = g_cnt[n];
    int end = start + deg;
    float acc0 = 0.f, acc1 = 0.f;
    int i = start;
    for (; i + 3 < end; i += 4) {
        int sA = g_srcs[i], sB = g_srcs[i + 1], sC = g_srcs[i + 2], sD = g_srcs[i + 3];
        float2 bA = *(const float2*)&g_B[sA * 64 + c];
        float2 bB = *(const float2*)&g_B[sB * 64 + c];
        float2 bC = *(const float2*)&g_B[sC * 64 + c];
        float2 bD = *(const float2*)&g_B[sD * 64 + c];
        float y;
        y = (a.x + bA.x) * sc0 + sh0; acc0 += fmaxf(y, NEG_SLOPE * y);
        y = (a.y + bA.y) * sc1 + sh1; acc1 += fmaxf(y, NEG_SLOPE * y);
        y = (a.x + bB.x) * sc0 + sh0; acc0 += fmaxf(y, NEG_SLOPE * y);
        y = (a.y + bB.y) * sc1 + sh1; acc1 += fmaxf(y, NEG_SLOPE * y);
        y = (a.x + bC.x) * sc0 + sh0; acc0 += fmaxf(y, NEG_SLOPE * y);
        y = (a.y + bC.y) * sc1 + sh1; acc1 += fmaxf(y, NEG_SLOPE * y);
        y = (a.x + bD.x) * sc0 + sh0; acc0 += fmaxf(y, NEG_SLOPE * y);
        y = (a.y + bD.y) * sc1 + sh1; acc1 += fmaxf(y, NEG_SLOPE * y);
    }
    for (; i < end; i++) {
        int sA = g_srcs[i];
        float2 bA = *(const float2*)&g_B[sA * 64 + c];
        float y;
        y = (a.x + bA.x) * sc0 + sh0; acc0 += fmaxf(y, NEG_SLOPE * y);
        y = (a.y + bA.y) * sc1 + sh1; acc1 += fmaxf(y, NEG_SLOPE * y);
    }
    float inv = 1.f / fmaxf((float)deg, 1.f);
    *(float2*)&out[n * 64 + c] = make_float2(acc0 * inv, acc1 * inv);
}

extern "C" void kernel_launch(void* const* d_in, const int* in_sizes, int n_in,
                              void* d_out, int out_size) {
    const float* feat = (const float*)d_in[0];
    const int* ei = (const int*)d_in[1];
    const float* W = (const float*)d_in[2];
    const float* b = (const float*)d_in[3];
    const float* gamma = (const float*)d_in[4];
    const float* beta = (const float*)d_in[5];
    float* out = (float*)d_out;

    int n_nodes = in_sizes[0] / DIMC;
    int E = in_sizes[1] / 2;
    if (n_nodes > N_MAX) n_nodes = N_MAX;
    if (E > E_MAX) E = E_MAX;

    int init_span = n_nodes > 64 * 128 ? n_nodes : 64 * 128;
    k_init<<<(init_span + 255) / 256, 256>>>(W, n_nodes);
    k_transform<<<(n_nodes + 63) / 64, 256>>>(feat, b, n_nodes);
    k_count<<<256, 256>>>(ei, E, n_nodes);
    int sblocks = (n_nodes + 1023) / 1024;
    k_scan1<<<sblocks, 1024>>>(n_nodes);
    k_scan2<<<1, 32>>>(sblocks);
    k_fill<<<1024, 256>>>(ei, E, n_nodes);
    k_stats<<<592, 256>>>(n_nodes);
    k_bnfinal<<<1, 64>>>(gamma, beta, E);
    k_gather<<<(n_nodes * 32 + 255) / 256, 256>>>(out, n_nodes);
}